// round 1
// baseline (speedup 1.0000x reference)
#include <cuda_runtime.h>
#include <math_constants.h>
#include <cstdint>

// ---------------------------------------------------------------------------
// MultiheadAttention  (T=2048, B=2, E=1024, H=16, D=64), fp32
//   1) qkv = x @ Win^T + b_in                GEMM-NT  M=4096 N=3072 K=1024
//   2) per (b,h): flash attention over T=2048, D=64  (online softmax)
//   3) out = attn @ Wout^T + b_out           GEMM-NT  M=4096 N=1024 K=1024
// ---------------------------------------------------------------------------

#define EMBED   1024
#define NHEAD   16
#define HDIM    64
#define TLEN    2048
#define BSZ     2
#define MROWS   (TLEN * BSZ)        // 4096
#define QKV_N   (3 * EMBED)         // 3072
#define SCALING 0.125f              // 64^-0.5

// Scratch (allocation-free rule: __device__ globals)
__device__ float g_qkv[(size_t)MROWS * QKV_N];   // [T,B,3E] == [4096,3072]
__device__ float g_attn[(size_t)MROWS * EMBED];  // [T,B,E]  == [4096,1024]

// ---------------------------------------------------------------------------
// GEMM-NT + bias:  C[M,N] = A[M,K] @ B[N,K]^T + bias[N]
// 128x128 block tile, BK=16, 256 threads, 8x8 per-thread micro-tile.
// M is fixed multiple of 128; N,K multiples of 128/16 (true for our shapes).
// ---------------------------------------------------------------------------
__global__ void __launch_bounds__(256) gemm_nt_bias(
    const float* __restrict__ A, const float* __restrict__ Bw,
    const float* __restrict__ bias, float* __restrict__ C,
    int N, int K)
{
    __shared__ float As[16][128];
    __shared__ float Bs[16][128];

    const int tid = threadIdx.x;
    const int tx  = tid & 15;       // 0..15 -> N direction
    const int ty  = tid >> 4;       // 0..15 -> M direction
    const int bm  = blockIdx.y;
    const int bn  = blockIdx.x;

    const float* Ab = A  + (size_t)bm * 128 * K;
    const float* Bb = Bw + (size_t)bn * 128 * K;

    float acc[8][8];
#pragma unroll
    for (int i = 0; i < 8; i++)
#pragma unroll
        for (int j = 0; j < 8; j++) acc[i][j] = 0.0f;

    for (int k0 = 0; k0 < K; k0 += 16) {
#pragma unroll
        for (int i = 0; i < 2; i++) {
            int idx = tid + i * 256;        // 0..511
            int row = idx >> 2;             // 0..127
            int c4  = (idx & 3) * 4;        // 0,4,8,12
            float4 av = *(const float4*)(Ab + (size_t)row * K + k0 + c4);
            As[c4 + 0][row] = av.x; As[c4 + 1][row] = av.y;
            As[c4 + 2][row] = av.z; As[c4 + 3][row] = av.w;
            float4 bv = *(const float4*)(Bb + (size_t)row * K + k0 + c4);
            Bs[c4 + 0][row] = bv.x; Bs[c4 + 1][row] = bv.y;
            Bs[c4 + 2][row] = bv.z; Bs[c4 + 3][row] = bv.w;
        }
        __syncthreads();

#pragma unroll
        for (int k = 0; k < 16; k++) {
            float a[8], b[8];
            *(float4*)&a[0] = *(const float4*)&As[k][ty * 8];
            *(float4*)&a[4] = *(const float4*)&As[k][ty * 8 + 4];
            *(float4*)&b[0] = *(const float4*)&Bs[k][tx * 8];
            *(float4*)&b[4] = *(const float4*)&Bs[k][tx * 8 + 4];
#pragma unroll
            for (int i = 0; i < 8; i++)
#pragma unroll
                for (int j = 0; j < 8; j++)
                    acc[i][j] += a[i] * b[j];
        }
        __syncthreads();
    }

#pragma unroll
    for (int i = 0; i < 8; i++) {
        int row = bm * 128 + ty * 8 + i;
#pragma unroll
        for (int j4 = 0; j4 < 2; j4++) {
            int col = bn * 128 + tx * 8 + j4 * 4;
            float4 o;
            o.x = acc[i][j4 * 4 + 0] + bias[col + 0];
            o.y = acc[i][j4 * 4 + 1] + bias[col + 1];
            o.z = acc[i][j4 * 4 + 2] + bias[col + 2];
            o.w = acc[i][j4 * 4 + 3] + bias[col + 3];
            *(float4*)(C + (size_t)row * N + col) = o;
        }
    }
}

// ---------------------------------------------------------------------------
// Flash attention: one block per (query-tile of 64, b*H+h).
// 256 threads: thread (rg, cg) = (tid>>4, tid&15) computes a 4x4 tile:
//   rows r0..r0+3 of the 64-row Q tile, score cols / output dims c0..c0+3.
// Online softmax with running (m, l); P staged through smem for the PV gemm.
// smem: Qs[64][64] + Ks[64][65] + Ps[64][64] = 49408 B (dynamic).
// ---------------------------------------------------------------------------
__global__ void __launch_bounds__(256) attn_kernel(
    const float* __restrict__ qkv, float* __restrict__ out)
{
    extern __shared__ float sm[];
    float* Qs = sm;                 // [64][64]
    float* Ks = sm + 64 * 64;       // [64][65]  (K tile, reused for V tile)
    float* Ps = Ks + 64 * 65;       // [64][64]

    const int tid = threadIdx.x;
    const int qt  = blockIdx.x;     // 0..31 query tile
    const int bh  = blockIdx.y;     // 0..31 = b*16 + h
    const int b   = bh >> 4;
    const int h   = bh & 15;
    const int rg  = tid >> 4;
    const int cg  = tid & 15;
    const int r0  = rg * 4;
    const int c0  = cg * 4;

    const size_t rs = (size_t)QKV_N;                  // stride per (t,b) row
    const float* qbase = qkv + (size_t)b * rs + (size_t)h * HDIM;
    const float* kbase = qbase + EMBED;
    const float* vbase = qbase + 2 * EMBED;

    // Load Q tile (scaled)
#pragma unroll
    for (int i = 0; i < 4; i++) {
        int e   = tid + i * 256;      // 0..1023
        int row = e >> 4;             // 0..63
        int c4  = (e & 15) * 4;       // 0..60
        int t   = qt * 64 + row;
        float4 v = *(const float4*)(qbase + (size_t)t * BSZ * rs + c4);
        float* dst = &Qs[row * 64 + c4];
        dst[0] = v.x * SCALING; dst[1] = v.y * SCALING;
        dst[2] = v.z * SCALING; dst[3] = v.w * SCALING;
    }

    float m[4], l[4], o[4][4];
#pragma unroll
    for (int i = 0; i < 4; i++) {
        m[i] = -CUDART_INF_F; l[i] = 0.0f;
#pragma unroll
        for (int j = 0; j < 4; j++) o[i][j] = 0.0f;
    }

    for (int kt = 0; kt < TLEN / 64; kt++) {
        __syncthreads();   // prior PV done reading Ks/Ps; Q stores visible (1st iter)

        // Load K tile
#pragma unroll
        for (int i = 0; i < 4; i++) {
            int e   = tid + i * 256;
            int row = e >> 4;
            int c4  = (e & 15) * 4;
            int s   = kt * 64 + row;
            float4 v = *(const float4*)(kbase + (size_t)s * BSZ * rs + c4);
            float* dst = &Ks[row * 65 + c4];
            dst[0] = v.x; dst[1] = v.y; dst[2] = v.z; dst[3] = v.w;
        }
        __syncthreads();

        // Scores: s4[i][j] = sum_d Q[r0+i][d] * K[c0+j][d]
        float s4[4][4];
#pragma unroll
        for (int i = 0; i < 4; i++)
#pragma unroll
            for (int j = 0; j < 4; j++) s4[i][j] = 0.0f;

#pragma unroll 8
        for (int d = 0; d < 64; d++) {
            float qv[4], kv[4];
#pragma unroll
            for (int i = 0; i < 4; i++) qv[i] = Qs[(r0 + i) * 64 + d];
#pragma unroll
            for (int j = 0; j < 4; j++) kv[j] = Ks[(c0 + j) * 65 + d];
#pragma unroll
            for (int i = 0; i < 4; i++)
#pragma unroll
                for (int j = 0; j < 4; j++)
                    s4[i][j] += qv[i] * kv[j];
        }

        // Online softmax update (per row; 16 cg-lanes cooperate via shfl)
#pragma unroll
        for (int i = 0; i < 4; i++) {
            float mx = fmaxf(fmaxf(s4[i][0], s4[i][1]), fmaxf(s4[i][2], s4[i][3]));
#pragma unroll
            for (int off = 1; off < 16; off <<= 1)
                mx = fmaxf(mx, __shfl_xor_sync(0xffffffffu, mx, off));
            float mn    = fmaxf(m[i], mx);
            float alpha = __expf(m[i] - mn);
            m[i] = mn;
            float ssum = 0.0f;
#pragma unroll
            for (int j = 0; j < 4; j++) {
                float p = __expf(s4[i][j] - mn);
                Ps[(r0 + i) * 64 + c0 + j] = p;
                ssum += p;
            }
#pragma unroll
            for (int off = 1; off < 16; off <<= 1)
                ssum += __shfl_xor_sync(0xffffffffu, ssum, off);
            l[i] = l[i] * alpha + ssum;
#pragma unroll
            for (int j = 0; j < 4; j++) o[i][j] *= alpha;
        }
        __syncthreads();   // Ps written; Ks free for V

        // Load V tile into Ks buffer
#pragma unroll
        for (int i = 0; i < 4; i++) {
            int e   = tid + i * 256;
            int row = e >> 4;
            int c4  = (e & 15) * 4;
            int s   = kt * 64 + row;
            float4 v = *(const float4*)(vbase + (size_t)s * BSZ * rs + c4);
            float* dst = &Ks[row * 65 + c4];
            dst[0] = v.x; dst[1] = v.y; dst[2] = v.z; dst[3] = v.w;
        }
        __syncthreads();

        // PV: o[i][j] += sum_c P[r0+i][c] * V[c][c0+j]
#pragma unroll 4
        for (int c = 0; c < 64; c++) {
            float pv[4], vv[4];
#pragma unroll
            for (int i = 0; i < 4; i++) pv[i] = Ps[(r0 + i) * 64 + c];
#pragma unroll
            for (int j = 0; j < 4; j++) vv[j] = Ks[c * 65 + c0 + j];
#pragma unroll
            for (int i = 0; i < 4; i++)
#pragma unroll
                for (int j = 0; j < 4; j++)
                    o[i][j] += pv[i] * vv[j];
        }
    }

    // Write normalized output to [T,B,E] layout
#pragma unroll
    for (int i = 0; i < 4; i++) {
        float inv = 1.0f / l[i];
        int t = qt * 64 + r0 + i;
        float4 v;
        v.x = o[i][0] * inv; v.y = o[i][1] * inv;
        v.z = o[i][2] * inv; v.w = o[i][3] * inv;
        *(float4*)(out + ((size_t)t * BSZ + b) * EMBED + h * HDIM + c0) = v;
    }
}

// ---------------------------------------------------------------------------
extern "C" void kernel_launch(void* const* d_in, const int* in_sizes, int n_in,
                              void* d_out, int out_size)
{
    const float* x     = (const float*)d_in[0];   // [2048,2,1024]
    const float* w_in  = (const float*)d_in[1];   // [3072,1024]
    const float* b_in  = (const float*)d_in[2];   // [3072]
    const float* w_out = (const float*)d_in[3];   // [1024,1024]
    const float* b_out = (const float*)d_in[4];   // [1024]
    float* out = (float*)d_out;                   // [2048,2,1024]

    void* qkv_p;  cudaGetSymbolAddress(&qkv_p, g_qkv);
    void* attn_p; cudaGetSymbolAddress(&attn_p, g_attn);
    float* qkv  = (float*)qkv_p;
    float* attn = (float*)attn_p;

    const int attn_smem = (64 * 64 + 64 * 65 + 64 * 64) * (int)sizeof(float); // 49408
    cudaFuncSetAttribute(attn_kernel,
                         cudaFuncAttributeMaxDynamicSharedMemorySize, attn_smem);

    // 1) QKV projection
    gemm_nt_bias<<<dim3(QKV_N / 128, MROWS / 128), 256>>>(x, w_in, b_in, qkv,
                                                          QKV_N, EMBED);
    // 2) Attention
    attn_kernel<<<dim3(TLEN / 64, BSZ * NHEAD), 256, attn_smem>>>(qkv, attn);
    // 3) Output projection
    gemm_nt_bias<<<dim3(EMBED / 128, MROWS / 128), 256>>>(attn, w_out, b_out, out,
                                                          EMBED, EMBED);
}

// round 3
// speedup vs baseline: 3.1581x; 3.1581x over previous
#include <cuda_runtime.h>
#include <cuda_bf16.h>
#include <math_constants.h>
#include <cstdint>

// ---------------------------------------------------------------------------
// MultiheadAttention (T=2048, B=2, E=1024, H=16, D=64) fp32, via bf16 HMMA
// (mma.sync m16n8k16) with hi/lo split precision. Plain-sm_100-safe subset:
// mma.sync + ldmatrix + cp.async only.
// ---------------------------------------------------------------------------

#define EMBED   1024
#define NHEAD   16
#define HDIM    64
#define TLEN    2048
#define BSZ     2
#define MROWS   4096
#define QKV_N   3072

// ------------------------------- scratch -----------------------------------
__device__ __nv_bfloat16 g_xhi [(size_t)MROWS * EMBED];
__device__ __nv_bfloat16 g_xlo [(size_t)MROWS * EMBED];
__device__ __nv_bfloat16 g_winhi[(size_t)QKV_N * EMBED];
__device__ __nv_bfloat16 g_winlo[(size_t)QKV_N * EMBED];
__device__ __nv_bfloat16 g_wohi[(size_t)EMBED * EMBED];
__device__ __nv_bfloat16 g_wolo[(size_t)EMBED * EMBED];
__device__ __nv_bfloat16 g_qkvhi[(size_t)MROWS * QKV_N];
__device__ __nv_bfloat16 g_qkvlo[(size_t)MROWS * QKV_N];
__device__ __nv_bfloat16 g_ahi [(size_t)MROWS * EMBED];
__device__ __nv_bfloat16 g_alo [(size_t)MROWS * EMBED];

// --------------------------- asm helpers -----------------------------------
__device__ __forceinline__ uint32_t smem_u32(const void* p) {
    uint32_t a;
    asm("{ .reg .u64 t; cvta.to.shared.u64 t, %1; cvt.u32.u64 %0, t; }"
        : "=r"(a) : "l"(p));
    return a;
}
__device__ __forceinline__ void ldsm4(uint32_t* r, uint32_t a) {
    asm volatile("ldmatrix.sync.aligned.m8n8.x4.shared.b16 {%0,%1,%2,%3}, [%4];"
        : "=r"(r[0]), "=r"(r[1]), "=r"(r[2]), "=r"(r[3]) : "r"(a));
}
__device__ __forceinline__ void ldsm4t(uint32_t* r, uint32_t a) {
    asm volatile("ldmatrix.sync.aligned.m8n8.x4.trans.shared.b16 {%0,%1,%2,%3}, [%4];"
        : "=r"(r[0]), "=r"(r[1]), "=r"(r[2]), "=r"(r[3]) : "r"(a));
}
__device__ __forceinline__ void mma_bf16(float* c, const uint32_t* a, const uint32_t* b) {
    asm volatile(
        "mma.sync.aligned.m16n8k16.row.col.f32.bf16.bf16.f32 "
        "{%0,%1,%2,%3}, {%4,%5,%6,%7}, {%8,%9}, {%0,%1,%2,%3};"
        : "+f"(c[0]), "+f"(c[1]), "+f"(c[2]), "+f"(c[3])
        : "r"(a[0]), "r"(a[1]), "r"(a[2]), "r"(a[3]), "r"(b[0]), "r"(b[1]));
}
__device__ __forceinline__ void cpa16(uint32_t dst, const void* src) {
    asm volatile("cp.async.cg.shared.global [%0], [%1], 16;" :: "r"(dst), "l"(src));
}
#define CP_COMMIT() asm volatile("cp.async.commit_group;")
#define CP_WAIT1()  asm volatile("cp.async.wait_group 1;")
#define CP_WAIT0()  asm volatile("cp.async.wait_group 0;")

__device__ __forceinline__ uint32_t packbf(float x, float y) {
    __nv_bfloat162 t = __floats2bfloat162_rn(x, y);
    return *(uint32_t*)&t;
}
__device__ __forceinline__ void store_hilo(
    __nv_bfloat16* hi, __nv_bfloat16* lo, size_t idx, float a, float b)
{
    __nv_bfloat16 h0 = __float2bfloat16(a), h1 = __float2bfloat16(b);
    __nv_bfloat16 l0 = __float2bfloat16(a - __bfloat162float(h0));
    __nv_bfloat16 l1 = __float2bfloat16(b - __bfloat162float(h1));
    *(__nv_bfloat162*)(hi + idx) = __nv_bfloat162(h0, h1);
    *(__nv_bfloat162*)(lo + idx) = __nv_bfloat162(l0, l1);
}

// ---------------------------------------------------------------------------
// fp32 -> bf16 hi/lo split
// ---------------------------------------------------------------------------
__global__ void __launch_bounds__(256) split_bf16(
    const float* __restrict__ src, __nv_bfloat16* __restrict__ hi,
    __nv_bfloat16* __restrict__ lo, int n4)
{
    int i = blockIdx.x * 256 + threadIdx.x;
    if (i >= n4) return;
    float4 v = *(const float4*)(src + (size_t)i * 4);
    store_hilo(hi, lo, (size_t)i * 4,     v.x, v.y);
    store_hilo(hi, lo, (size_t)i * 4 + 2, v.z, v.w);
}

// ---------------------------------------------------------------------------
// HMMA GEMM-NT + bias: C[M,N] = (Ahi+Alo)[M,K] @ (Bhi+Blo)[N,K]^T + bias
// 128x128 CTA tile, BK=32, 8 warps (2x4), warp tile 64x32, cp.async 2-stage.
// Smem rows padded to 40 bf16 (80B) for conflict-free ldmatrix.
// ---------------------------------------------------------------------------
#define GSTRIDE 40
#define GTILEB  (128 * GSTRIDE * 2)   // 10240 B
#define GSTAGE  (4 * GTILEB)          // 40960 B

template<bool SPLIT>
__global__ void __launch_bounds__(256) gemm_mma(
    const __nv_bfloat16* __restrict__ Ahi, const __nv_bfloat16* __restrict__ Alo,
    const __nv_bfloat16* __restrict__ Bhi, const __nv_bfloat16* __restrict__ Blo,
    const float* __restrict__ bias, float* __restrict__ Cf,
    __nv_bfloat16* __restrict__ Chi, __nv_bfloat16* __restrict__ Clo,
    int N, int K)
{
    extern __shared__ char smem[];
    const uint32_t sbase = smem_u32(smem);
    const int tid = threadIdx.x, wid = tid >> 5, lane = tid & 31;
    const int bm = blockIdx.y, bn = blockIdx.x;
    const int wm = wid >> 2, wn = wid & 3;

    float acc[4][4][4];
#pragma unroll
    for (int a = 0; a < 4; a++)
#pragma unroll
        for (int b = 0; b < 4; b++)
#pragma unroll
            for (int c = 0; c < 4; c++) acc[a][b][c] = 0.0f;

    auto prefetch = [&](int it) {
        const int k0 = it << 5;
        const int buf = it & 1;
#pragma unroll
        for (int i = 0; i < 8; i++) {
            int g = tid + i * 256;            // 0..2047
            int t = g >> 9;                   // tensor 0..3 (uniform per i)
            int c = g & 511;
            int row = c >> 2, c16 = c & 3;
            const __nv_bfloat16* P = (t == 0) ? Ahi : (t == 1) ? Alo
                                   : (t == 2) ? Bhi : Blo;
            int rb = (t < 2) ? bm * 128 : bn * 128;
            const void* src = P + (size_t)(rb + row) * K + k0 + c16 * 8;
            uint32_t dst = sbase + buf * GSTAGE + t * GTILEB
                         + (row * GSTRIDE + c16 * 8) * 2;
            cpa16(dst, src);
        }
        CP_COMMIT();
    };

    const int niter = K >> 5;
    prefetch(0);
    for (int it = 0; it < niter; it++) {
        if (it + 1 < niter) { prefetch(it + 1); CP_WAIT1(); }
        else                { CP_WAIT0(); }
        __syncthreads();

        const uint32_t st   = sbase + (it & 1) * GSTAGE;
        const uint32_t tAhi = st,               tAlo = st + GTILEB;
        const uint32_t tBhi = st + 2 * GTILEB,  tBlo = st + 3 * GTILEB;

        const int ar = lane & 15, ac = (lane >> 4) * 8;
        const int br = (lane & 7) + ((lane & 16) ? 8 : 0);
        const int bc = (lane & 8) ? 8 : 0;

#pragma unroll
        for (int ks = 0; ks < 2; ks++) {
            const int k0 = ks * 16;
            uint32_t ah[4][4], al[4][4], bh[4][2], bl[4][2];
#pragma unroll
            for (int mi = 0; mi < 4; mi++) {
                uint32_t off = ((wm * 64 + mi * 16 + ar) * GSTRIDE + k0 + ac) * 2;
                ldsm4(ah[mi], tAhi + off);
                ldsm4(al[mi], tAlo + off);
            }
#pragma unroll
            for (int p = 0; p < 2; p++) {
                uint32_t off = ((wn * 32 + p * 16 + br) * GSTRIDE + k0 + bc) * 2;
                uint32_t r[4];
                ldsm4(r, tBhi + off);
                bh[2*p][0] = r[0]; bh[2*p][1] = r[1];
                bh[2*p+1][0] = r[2]; bh[2*p+1][1] = r[3];
                ldsm4(r, tBlo + off);
                bl[2*p][0] = r[0]; bl[2*p][1] = r[1];
                bl[2*p+1][0] = r[2]; bl[2*p+1][1] = r[3];
            }
#pragma unroll
            for (int mi = 0; mi < 4; mi++)
#pragma unroll
                for (int ni = 0; ni < 4; ni++) {
                    mma_bf16(acc[mi][ni], ah[mi], bh[ni]);
                    mma_bf16(acc[mi][ni], ah[mi], bl[ni]);
                    mma_bf16(acc[mi][ni], al[mi], bh[ni]);
                }
        }
        __syncthreads();
    }

    // epilogue
    const int r = lane >> 2, q = lane & 3;
#pragma unroll
    for (int mi = 0; mi < 4; mi++) {
#pragma unroll
        for (int ni = 0; ni < 4; ni++) {
            int row = bm * 128 + wm * 64 + mi * 16 + r;
            int col = bn * 128 + wn * 32 + ni * 8 + 2 * q;
            float b0 = bias[col], b1 = bias[col + 1];
            float v0 = acc[mi][ni][0] + b0, v1 = acc[mi][ni][1] + b1;
            float v2 = acc[mi][ni][2] + b0, v3 = acc[mi][ni][3] + b1;
            if (SPLIT) {
                store_hilo(Chi, Clo, (size_t)row * N + col, v0, v1);
                store_hilo(Chi, Clo, (size_t)(row + 8) * N + col, v2, v3);
            } else {
                *(float2*)(Cf + (size_t)row * N + col)       = make_float2(v0, v1);
                *(float2*)(Cf + (size_t)(row + 8) * N + col) = make_float2(v2, v3);
            }
        }
    }
}

// ---------------------------------------------------------------------------
// Flash attention via HMMA. Block = (q-tile 64, b*H+h), 128 threads (4 warps).
// Warp w owns q rows 16w..16w+15. QK^T: 3-pass hi/lo. PV: bf16 single-pass
// (P exact-ish in [0,1], V=hi only). Online softmax in fp32 C fragments.
// smem tiles [64][72] bf16: Qhi,Qlo,Khi,Klo,V  (46080 B).
// ---------------------------------------------------------------------------
#define AST 72
#define ATB (64 * AST * 2)   // 9216 B

__global__ void __launch_bounds__(128) attn_mma(
    const __nv_bfloat16* __restrict__ qh_, const __nv_bfloat16* __restrict__ ql_,
    __nv_bfloat16* __restrict__ ohi, __nv_bfloat16* __restrict__ olo)
{
    extern __shared__ char smem[];
    const uint32_t sb = smem_u32(smem);
    const uint32_t sQh = sb, sQl = sb + ATB, sKh = sb + 2 * ATB,
                   sKl = sb + 3 * ATB, sV = sb + 4 * ATB;

    const int tid = threadIdx.x, wid = tid >> 5, lane = tid & 31;
    const int qt = blockIdx.x, bh = blockIdx.y, b = bh >> 4, h = bh & 15;

    // ---- load Q tiles (scaled by 0.125 — exact in bf16) ----
    const __nv_bfloat162 s2 = __floats2bfloat162_rn(0.125f, 0.125f);
#pragma unroll
    for (int i = 0; i < 4; i++) {
        int c = tid + i * 128;          // 0..511
        int row = c >> 3, c16 = c & 7;
        int t = qt * 64 + row;
        size_t goff = ((size_t)(t * 2 + b)) * QKV_N + h * 64 + c16 * 8;
        uint4 vh = *(const uint4*)(qh_ + goff);
        uint4 vl = *(const uint4*)(ql_ + goff);
        __nv_bfloat162* ph = (__nv_bfloat162*)&vh;
        __nv_bfloat162* pl = (__nv_bfloat162*)&vl;
#pragma unroll
        for (int j = 0; j < 4; j++) { ph[j] = __hmul2(ph[j], s2); pl[j] = __hmul2(pl[j], s2); }
        *(uint4*)(smem + 0 * ATB + (row * AST + c16 * 8) * 2) = vh;
        *(uint4*)(smem + 1 * ATB + (row * AST + c16 * 8) * 2) = vl;
    }
    __syncthreads();

    // ---- preload Q fragments ----
    uint32_t qfh[4][4], qfl[4][4];
    {
        const int ar = lane & 15, ac = (lane >> 4) * 8;
#pragma unroll
        for (int kt = 0; kt < 4; kt++) {
            uint32_t off = ((wid * 16 + ar) * AST + kt * 16 + ac) * 2;
            ldsm4(qfh[kt], sQh + off);
            ldsm4(qfl[kt], sQl + off);
        }
    }

    float O[8][4];
#pragma unroll
    for (int i = 0; i < 8; i++)
#pragma unroll
        for (int j = 0; j < 4; j++) O[i][j] = 0.0f;
    float m0 = -CUDART_INF_F, m1 = -CUDART_INF_F, l0 = 0.0f, l1 = 0.0f;

    for (int st = 0; st < TLEN / 64; st++) {
        __syncthreads();
        // ---- load K (hi,lo) and V (hi) tiles ----
#pragma unroll
        for (int i = 0; i < 4; i++) {
            int c = tid + i * 128;
            int row = c >> 3, c16 = c & 7;
            int s = st * 64 + row;
            size_t base = ((size_t)(s * 2 + b)) * QKV_N + h * 64 + c16 * 8;
            uint32_t doff = (row * AST + c16 * 8) * 2;
            *(uint4*)(smem + 2 * ATB + doff) = *(const uint4*)(qh_ + base + EMBED);
            *(uint4*)(smem + 3 * ATB + doff) = *(const uint4*)(ql_ + base + EMBED);
            *(uint4*)(smem + 4 * ATB + doff) = *(const uint4*)(qh_ + base + 2 * EMBED);
        }
        __syncthreads();

        // ---- S = Q K^T (3-pass) ----
        float s4[8][4];
#pragma unroll
        for (int i = 0; i < 8; i++)
#pragma unroll
            for (int j = 0; j < 4; j++) s4[i][j] = 0.0f;

        const int br = (lane & 7) + ((lane & 16) ? 8 : 0);
        const int bc = (lane & 8) ? 8 : 0;
#pragma unroll
        for (int kt = 0; kt < 4; kt++) {
            uint32_t kh[8][2], kl[8][2];
#pragma unroll
            for (int p = 0; p < 4; p++) {
                uint32_t off = ((p * 16 + br) * AST + kt * 16 + bc) * 2;
                uint32_t r[4];
                ldsm4(r, sKh + off);
                kh[2*p][0] = r[0]; kh[2*p][1] = r[1];
                kh[2*p+1][0] = r[2]; kh[2*p+1][1] = r[3];
                ldsm4(r, sKl + off);
                kl[2*p][0] = r[0]; kl[2*p][1] = r[1];
                kl[2*p+1][0] = r[2]; kl[2*p+1][1] = r[3];
            }
#pragma unroll
            for (int nt = 0; nt < 8; nt++) {
                mma_bf16(s4[nt], qfh[kt], kh[nt]);
                mma_bf16(s4[nt], qfh[kt], kl[nt]);
                mma_bf16(s4[nt], qfl[kt], kh[nt]);
            }
        }

        // ---- online softmax (rows r=lane/4 and r+8) ----
        float mx0 = -CUDART_INF_F, mx1 = -CUDART_INF_F;
#pragma unroll
        for (int nt = 0; nt < 8; nt++) {
            mx0 = fmaxf(mx0, fmaxf(s4[nt][0], s4[nt][1]));
            mx1 = fmaxf(mx1, fmaxf(s4[nt][2], s4[nt][3]));
        }
        mx0 = fmaxf(mx0, __shfl_xor_sync(0xffffffffu, mx0, 1));
        mx0 = fmaxf(mx0, __shfl_xor_sync(0xffffffffu, mx0, 2));
        mx1 = fmaxf(mx1, __shfl_xor_sync(0xffffffffu, mx1, 1));
        mx1 = fmaxf(mx1, __shfl_xor_sync(0xffffffffu, mx1, 2));

        float mn0 = fmaxf(m0, mx0), mn1 = fmaxf(m1, mx1);
        float a0 = __expf(m0 - mn0), a1 = __expf(m1 - mn1);
        m0 = mn0; m1 = mn1;
        float sum0 = 0.0f, sum1 = 0.0f;
#pragma unroll
        for (int nt = 0; nt < 8; nt++) {
            s4[nt][0] = __expf(s4[nt][0] - mn0); sum0 += s4[nt][0];
            s4[nt][1] = __expf(s4[nt][1] - mn0); sum0 += s4[nt][1];
            s4[nt][2] = __expf(s4[nt][2] - mn1); sum1 += s4[nt][2];
            s4[nt][3] = __expf(s4[nt][3] - mn1); sum1 += s4[nt][3];
        }
        sum0 += __shfl_xor_sync(0xffffffffu, sum0, 1);
        sum0 += __shfl_xor_sync(0xffffffffu, sum0, 2);
        sum1 += __shfl_xor_sync(0xffffffffu, sum1, 1);
        sum1 += __shfl_xor_sync(0xffffffffu, sum1, 2);
        l0 = l0 * a0 + sum0;
        l1 = l1 * a1 + sum1;
#pragma unroll
        for (int nt = 0; nt < 8; nt++) {
            O[nt][0] *= a0; O[nt][1] *= a0; O[nt][2] *= a1; O[nt][3] *= a1;
        }

        // ---- P fragments (C->A reuse) ----
        uint32_t pa[4][4];
#pragma unroll
        for (int jj = 0; jj < 4; jj++) {
            pa[jj][0] = packbf(s4[2*jj][0],   s4[2*jj][1]);
            pa[jj][1] = packbf(s4[2*jj][2],   s4[2*jj][3]);
            pa[jj][2] = packbf(s4[2*jj+1][0], s4[2*jj+1][1]);
            pa[jj][3] = packbf(s4[2*jj+1][2], s4[2*jj+1][3]);
        }

        // ---- O += P V ----
        const int vr = lane & 15, vc = (lane >> 4) * 8;
#pragma unroll
        for (int kt = 0; kt < 4; kt++) {
#pragma unroll
            for (int p = 0; p < 4; p++) {
                uint32_t r[4];
                ldsm4t(r, sV + ((kt * 16 + vr) * AST + p * 16 + vc) * 2);
                mma_bf16(O[2*p],   pa[kt], r);
                mma_bf16(O[2*p+1], pa[kt], r + 2);
            }
        }
    }

    // ---- epilogue: normalize, write bf16 hi/lo ----
    const float inv0 = 1.0f / l0, inv1 = 1.0f / l1;
    const int r = lane >> 2, q = lane & 3;
    const int t0 = qt * 64 + wid * 16 + r;
#pragma unroll
    for (int nt = 0; nt < 8; nt++) {
        int d = nt * 8 + 2 * q;
        size_t i0 = ((size_t)(t0 * 2 + b)) * EMBED + h * 64 + d;
        size_t i1 = ((size_t)((t0 + 8) * 2 + b)) * EMBED + h * 64 + d;
        store_hilo(ohi, olo, i0, O[nt][0] * inv0, O[nt][1] * inv0);
        store_hilo(ohi, olo, i1, O[nt][2] * inv1, O[nt][3] * inv1);
    }
}

// ---------------------------------------------------------------------------
extern "C" void kernel_launch(void* const* d_in, const int* in_sizes, int n_in,
                              void* d_out, int out_size)
{
    const float* x     = (const float*)d_in[0];
    const float* w_in  = (const float*)d_in[1];
    const float* b_in  = (const float*)d_in[2];
    const float* w_out = (const float*)d_in[3];
    const float* b_out = (const float*)d_in[4];
    float* out = (float*)d_out;

    void *xhi, *xlo, *winhi, *winlo, *wohi, *wolo, *qkvhi, *qkvlo, *ahi, *alo;
    cudaGetSymbolAddress(&xhi, g_xhi);     cudaGetSymbolAddress(&xlo, g_xlo);
    cudaGetSymbolAddress(&winhi, g_winhi); cudaGetSymbolAddress(&winlo, g_winlo);
    cudaGetSymbolAddress(&wohi, g_wohi);   cudaGetSymbolAddress(&wolo, g_wolo);
    cudaGetSymbolAddress(&qkvhi, g_qkvhi); cudaGetSymbolAddress(&qkvlo, g_qkvlo);
    cudaGetSymbolAddress(&ahi, g_ahi);     cudaGetSymbolAddress(&alo, g_alo);

    const int gemm_smem = 2 * GSTAGE;        // 81920
    const int attn_smem = 5 * ATB;           // 46080
    cudaFuncSetAttribute(gemm_mma<true>,
        cudaFuncAttributeMaxDynamicSharedMemorySize, gemm_smem);
    cudaFuncSetAttribute(gemm_mma<false>,
        cudaFuncAttributeMaxDynamicSharedMemorySize, gemm_smem);
    cudaFuncSetAttribute(attn_mma,
        cudaFuncAttributeMaxDynamicSharedMemorySize, attn_smem);

    // splits
    int n4 = MROWS * EMBED / 4;
    split_bf16<<<(n4 + 255) / 256, 256>>>(x, (__nv_bfloat16*)xhi,
                                          (__nv_bfloat16*)xlo, n4);
    n4 = QKV_N * EMBED / 4;
    split_bf16<<<(n4 + 255) / 256, 256>>>(w_in, (__nv_bfloat16*)winhi,
                                          (__nv_bfloat16*)winlo, n4);
    n4 = EMBED * EMBED / 4;
    split_bf16<<<(n4 + 255) / 256, 256>>>(w_out, (__nv_bfloat16*)wohi,
                                          (__nv_bfloat16*)wolo, n4);

    // 1) QKV projection -> bf16 hi/lo qkv
    gemm_mma<true><<<dim3(QKV_N / 128, MROWS / 128), 256, gemm_smem>>>(
        (const __nv_bfloat16*)xhi, (const __nv_bfloat16*)xlo,
        (const __nv_bfloat16*)winhi, (const __nv_bfloat16*)winlo,
        b_in, nullptr,
        (__nv_bfloat16*)qkvhi, (__nv_bfloat16*)qkvlo, QKV_N, EMBED);

    // 2) attention -> bf16 hi/lo attn
    attn_mma<<<dim3(TLEN / 64, BSZ * NHEAD), 128, attn_smem>>>(
        (const __nv_bfloat16*)qkvhi, (const __nv_bfloat16*)qkvlo,
        (__nv_bfloat16*)ahi, (__nv_bfloat16*)alo);

    // 3) output projection -> fp32 out
    gemm_mma<false><<<dim3(EMBED / 128, MROWS / 128), 256, gemm_smem>>>(
        (const __nv_bfloat16*)ahi, (const __nv_bfloat16*)alo,
        (const __nv_bfloat16*)wohi, (const __nv_bfloat16*)wolo,
        b_out, out, nullptr, nullptr, EMBED, EMBED);
}

// round 5
// speedup vs baseline: 4.0412x; 1.2796x over previous
#include <cuda_runtime.h>
#include <cuda_bf16.h>
#include <cuda_fp16.h>
#include <math_constants.h>
#include <cstdint>

// ---------------------------------------------------------------------------
// MultiheadAttention (T=2048, B=2, E=1024, H=16, D=64) fp32.
// QKV/out projections: 3-pass bf16-split HMMA (fp32-grade accuracy).
// Attention: fp16 HMMA, 1-pass QK^T + 1-pass PV, fp32 softmax.
// ---------------------------------------------------------------------------

#define EMBED   1024
#define NHEAD   16
#define HDIM    64
#define TLEN    2048
#define BSZ     2
#define MROWS   4096
#define QKV_N   3072

// ------------------------------- scratch -----------------------------------
__device__ __nv_bfloat16 g_xhi [(size_t)MROWS * EMBED];
__device__ __nv_bfloat16 g_xlo [(size_t)MROWS * EMBED];
__device__ __nv_bfloat16 g_winhi[(size_t)QKV_N * EMBED];
__device__ __nv_bfloat16 g_winlo[(size_t)QKV_N * EMBED];
__device__ __nv_bfloat16 g_wohi[(size_t)EMBED * EMBED];
__device__ __nv_bfloat16 g_wolo[(size_t)EMBED * EMBED];
__device__ __half        g_qkvh[(size_t)MROWS * QKV_N];
__device__ __nv_bfloat16 g_ahi [(size_t)MROWS * EMBED];
__device__ __nv_bfloat16 g_alo [(size_t)MROWS * EMBED];

// --------------------------- asm helpers -----------------------------------
__device__ __forceinline__ uint32_t smem_u32(const void* p) {
    uint32_t a;
    asm("{ .reg .u64 t; cvta.to.shared.u64 t, %1; cvt.u32.u64 %0, t; }"
        : "=r"(a) : "l"(p));
    return a;
}
__device__ __forceinline__ void ldsm4(uint32_t* r, uint32_t a) {
    asm volatile("ldmatrix.sync.aligned.m8n8.x4.shared.b16 {%0,%1,%2,%3}, [%4];"
        : "=r"(r[0]), "=r"(r[1]), "=r"(r[2]), "=r"(r[3]) : "r"(a));
}
__device__ __forceinline__ void ldsm4t(uint32_t* r, uint32_t a) {
    asm volatile("ldmatrix.sync.aligned.m8n8.x4.trans.shared.b16 {%0,%1,%2,%3}, [%4];"
        : "=r"(r[0]), "=r"(r[1]), "=r"(r[2]), "=r"(r[3]) : "r"(a));
}
__device__ __forceinline__ void mma_bf16(float* c, const uint32_t* a, const uint32_t* b) {
    asm volatile(
        "mma.sync.aligned.m16n8k16.row.col.f32.bf16.bf16.f32 "
        "{%0,%1,%2,%3}, {%4,%5,%6,%7}, {%8,%9}, {%0,%1,%2,%3};"
        : "+f"(c[0]), "+f"(c[1]), "+f"(c[2]), "+f"(c[3])
        : "r"(a[0]), "r"(a[1]), "r"(a[2]), "r"(a[3]), "r"(b[0]), "r"(b[1]));
}
__device__ __forceinline__ void mma_f16(float* c, const uint32_t* a, const uint32_t* b) {
    asm volatile(
        "mma.sync.aligned.m16n8k16.row.col.f32.f16.f16.f32 "
        "{%0,%1,%2,%3}, {%4,%5,%6,%7}, {%8,%9}, {%0,%1,%2,%3};"
        : "+f"(c[0]), "+f"(c[1]), "+f"(c[2]), "+f"(c[3])
        : "r"(a[0]), "r"(a[1]), "r"(a[2]), "r"(a[3]), "r"(b[0]), "r"(b[1]));
}
__device__ __forceinline__ void cpa16(uint32_t dst, const void* src) {
    asm volatile("cp.async.cg.shared.global [%0], [%1], 16;" :: "r"(dst), "l"(src));
}
#define CP_COMMIT() asm volatile("cp.async.commit_group;")
#define CP_WAIT0()  asm volatile("cp.async.wait_group 0;")

__device__ __forceinline__ uint32_t packh(float x, float y) {
    __half2 t = __floats2half2_rn(x, y);
    return *(uint32_t*)&t;
}
__device__ __forceinline__ void store_hilo(
    __nv_bfloat16* hi, __nv_bfloat16* lo, size_t idx, float a, float b)
{
    __nv_bfloat16 h0 = __float2bfloat16(a), h1 = __float2bfloat16(b);
    __nv_bfloat16 l0 = __float2bfloat16(a - __bfloat162float(h0));
    __nv_bfloat16 l1 = __float2bfloat16(b - __bfloat162float(h1));
    *(__nv_bfloat162*)(hi + idx) = __nv_bfloat162(h0, h1);
    *(__nv_bfloat162*)(lo + idx) = __nv_bfloat162(l0, l1);
}

// ---------------------------------------------------------------------------
__global__ void __launch_bounds__(256) split_bf16(
    const float* __restrict__ src, __nv_bfloat16* __restrict__ hi,
    __nv_bfloat16* __restrict__ lo, int n4)
{
    int i = blockIdx.x * 256 + threadIdx.x;
    if (i >= n4) return;
    float4 v = *(const float4*)(src + (size_t)i * 4);
    store_hilo(hi, lo, (size_t)i * 4,     v.x, v.y);
    store_hilo(hi, lo, (size_t)i * 4 + 2, v.z, v.w);
}

// ---------------------------------------------------------------------------
// HMMA GEMM-NT + bias (3-pass bf16 split).  MODE 0: fp32 out. MODE 2: fp16 out.
// 128x128 CTA tile, BK=32, 8 warps, warp tile 64x32, cp.async 2-stage,
// single __syncthreads per K-step.
// ---------------------------------------------------------------------------
#define GSTRIDE 40
#define GTILEB  (128 * GSTRIDE * 2)   // 10240 B
#define GSTAGE  (4 * GTILEB)          // 40960 B

template<int MODE>
__global__ void __launch_bounds__(256) gemm_mma(
    const __nv_bfloat16* __restrict__ Ahi, const __nv_bfloat16* __restrict__ Alo,
    const __nv_bfloat16* __restrict__ Bhi, const __nv_bfloat16* __restrict__ Blo,
    const float* __restrict__ bias, float* __restrict__ Cf,
    __half* __restrict__ Ch, int N, int K)
{
    extern __shared__ char smem[];
    const uint32_t sbase = smem_u32(smem);
    const int tid = threadIdx.x, wid = tid >> 5, lane = tid & 31;
    const int bm = blockIdx.y, bn = blockIdx.x;
    const int wm = wid >> 2, wn = wid & 3;

    float acc[4][4][4];
#pragma unroll
    for (int a = 0; a < 4; a++)
#pragma unroll
        for (int b = 0; b < 4; b++)
#pragma unroll
            for (int c = 0; c < 4; c++) acc[a][b][c] = 0.0f;

    auto prefetch = [&](int it) {
        const int k0 = it << 5;
        const int buf = it & 1;
#pragma unroll
        for (int i = 0; i < 8; i++) {
            int g = tid + i * 256;
            int t = g >> 9;
            int c = g & 511;
            int row = c >> 2, c16 = c & 3;
            const __nv_bfloat16* P = (t == 0) ? Ahi : (t == 1) ? Alo
                                   : (t == 2) ? Bhi : Blo;
            int rb = (t < 2) ? bm * 128 : bn * 128;
            const void* src = P + (size_t)(rb + row) * K + k0 + c16 * 8;
            uint32_t dst = sbase + buf * GSTAGE + t * GTILEB
                         + (row * GSTRIDE + c16 * 8) * 2;
            cpa16(dst, src);
        }
        CP_COMMIT();
    };

    const int niter = K >> 5;
    prefetch(0);
    for (int it = 0; it < niter; it++) {
        CP_WAIT0();
        __syncthreads();
        if (it + 1 < niter) prefetch(it + 1);

        const uint32_t st   = sbase + (it & 1) * GSTAGE;
        const uint32_t tAhi = st,               tAlo = st + GTILEB;
        const uint32_t tBhi = st + 2 * GTILEB,  tBlo = st + 3 * GTILEB;

        const int ar = lane & 15, ac = (lane >> 4) * 8;
        const int br = (lane & 7) + ((lane & 16) ? 8 : 0);
        const int bc = (lane & 8) ? 8 : 0;

#pragma unroll
        for (int ks = 0; ks < 2; ks++) {
            const int k0 = ks * 16;
            uint32_t ah[4][4], al[4][4], bh[4][2], bl[4][2];
#pragma unroll
            for (int mi = 0; mi < 4; mi++) {
                uint32_t off = ((wm * 64 + mi * 16 + ar) * GSTRIDE + k0 + ac) * 2;
                ldsm4(ah[mi], tAhi + off);
                ldsm4(al[mi], tAlo + off);
            }
#pragma unroll
            for (int p = 0; p < 2; p++) {
                uint32_t off = ((wn * 32 + p * 16 + br) * GSTRIDE + k0 + bc) * 2;
                uint32_t r[4];
                ldsm4(r, tBhi + off);
                bh[2*p][0] = r[0]; bh[2*p][1] = r[1];
                bh[2*p+1][0] = r[2]; bh[2*p+1][1] = r[3];
                ldsm4(r, tBlo + off);
                bl[2*p][0] = r[0]; bl[2*p][1] = r[1];
                bl[2*p+1][0] = r[2]; bl[2*p+1][1] = r[3];
            }
#pragma unroll
            for (int mi = 0; mi < 4; mi++)
#pragma unroll
                for (int ni = 0; ni < 4; ni++) {
                    mma_bf16(acc[mi][ni], ah[mi], bh[ni]);
                    mma_bf16(acc[mi][ni], ah[mi], bl[ni]);
                    mma_bf16(acc[mi][ni], al[mi], bh[ni]);
                }
        }
    }

    const int r = lane >> 2, q = lane & 3;
#pragma unroll
    for (int mi = 0; mi < 4; mi++) {
#pragma unroll
        for (int ni = 0; ni < 4; ni++) {
            int row = bm * 128 + wm * 64 + mi * 16 + r;
            int col = bn * 128 + wn * 32 + ni * 8 + 2 * q;
            float b0 = bias[col], b1 = bias[col + 1];
            float v0 = acc[mi][ni][0] + b0, v1 = acc[mi][ni][1] + b1;
            float v2 = acc[mi][ni][2] + b0, v3 = acc[mi][ni][3] + b1;
            if (MODE == 0) {
                *(float2*)(Cf + (size_t)row * N + col)       = make_float2(v0, v1);
                *(float2*)(Cf + (size_t)(row + 8) * N + col) = make_float2(v2, v3);
            } else {
                *(__half2*)(Ch + (size_t)row * N + col)       = __floats2half2_rn(v0, v1);
                *(__half2*)(Ch + (size_t)(row + 8) * N + col) = __floats2half2_rn(v2, v3);
            }
        }
    }
}

// ---------------------------------------------------------------------------
// Flash attention, fp16 HMMA. Block = (q-tile 128, b*H+h), 256 threads/8 warps.
// Warp w owns q rows 16w..16w+15. QK^T 1-pass, PV 1-pass, fp32 softmax with
// l accumulated from fp16-rounded P (numerator/denominator cancellation).
// smem: Qstage 128x72 fp16 (18432 B) + 2x(K,V) 64x72 fp16 (4x9216 B) = 55296 B.
// ---------------------------------------------------------------------------
#define AST  72
#define ATBF (64 * AST * 2)     // 9216 B per K/V tile
#define QSTG (128 * AST * 2)    // 18432 B

__global__ void __launch_bounds__(256) attn_f16(
    const __half* __restrict__ qkv,
    __nv_bfloat16* __restrict__ ohi, __nv_bfloat16* __restrict__ olo)
{
    extern __shared__ char smem[];
    const uint32_t sb  = smem_u32(smem);
    const uint32_t sQ  = sb;
    const uint32_t sKV = sb + QSTG;

    const int tid = threadIdx.x, wid = tid >> 5, lane = tid & 31;
    const int qt = blockIdx.x, bh = blockIdx.y, b = bh >> 4, h = bh & 15;

    // K tile (8 KB) + V tile (8 KB) per stage = 1024 x 16B transfers.
    auto pf = [&](int st) {
        const int buf = st & 1;
#pragma unroll
        for (int i = 0; i < 4; i++) {
            int c  = tid + i * 256;        // 0..1023
            int kv = c >> 9;               // 0=K, 1=V
            int e  = c & 511;
            int row = e >> 3, ch = e & 7;  // row 0..63, ch 0..7 (8 halves each)
            const void* src = qkv + ((size_t)((st * 64 + row) * 2 + b)) * QKV_N
                            + (kv ? 2 * EMBED : EMBED) + h * 64 + ch * 8;
            uint32_t dst = sKV + (buf * 2 + kv) * ATBF + (row * AST + ch * 8) * 2;
            cpa16(dst, src);
        }
        CP_COMMIT();
    };

    pf(0);

    // ---- stage Q (scaled by 0.125, exact in fp16) ----
    const __half2 s2 = __floats2half2_rn(0.125f, 0.125f);
#pragma unroll
    for (int i = 0; i < 4; i++) {
        int c = tid + i * 256;             // 0..1023
        int row = c >> 3, ch = c & 7;
        int t = qt * 128 + row;
        uint4 v = *(const uint4*)(qkv + ((size_t)(t * 2 + b)) * QKV_N + h * 64 + ch * 8);
        __half2* p = (__half2*)&v;
#pragma unroll
        for (int j = 0; j < 4; j++) p[j] = __hmul2(p[j], s2);
        *(uint4*)(smem + (row * AST + ch * 8) * 2) = v;
    }
    __syncthreads();

    // ---- preload Q fragments ----
    uint32_t qf[4][4];
    {
        const int ar = lane & 15, ac = (lane >> 4) * 8;
#pragma unroll
        for (int kt = 0; kt < 4; kt++)
            ldsm4(qf[kt], sQ + ((wid * 16 + ar) * AST + kt * 16 + ac) * 2);
    }

    float O[8][4];
#pragma unroll
    for (int i = 0; i < 8; i++)
#pragma unroll
        for (int j = 0; j < 4; j++) O[i][j] = 0.0f;
    float m0 = -CUDART_INF_F, m1 = -CUDART_INF_F, l0 = 0.0f, l1 = 0.0f;

    const int br = (lane & 7) + ((lane & 16) ? 8 : 0);
    const int bc = (lane & 8) ? 8 : 0;
    const int vr = lane & 15, vc = (lane >> 4) * 8;

    for (int st = 0; st < TLEN / 64; st++) {
        CP_WAIT0();
        __syncthreads();
        if (st + 1 < TLEN / 64) pf(st + 1);

        const uint32_t sK = sKV + ((st & 1) * 2) * ATBF;
        const uint32_t sV = sK + ATBF;

        // ---- S = Q K^T ----
        float s4[8][4];
#pragma unroll
        for (int i = 0; i < 8; i++)
#pragma unroll
            for (int j = 0; j < 4; j++) s4[i][j] = 0.0f;

#pragma unroll
        for (int kt = 0; kt < 4; kt++) {
            uint32_t kh[8][2];
#pragma unroll
            for (int p = 0; p < 4; p++) {
                uint32_t r[4];
                ldsm4(r, sK + ((p * 16 + br) * AST + kt * 16 + bc) * 2);
                kh[2*p][0] = r[0]; kh[2*p][1] = r[1];
                kh[2*p+1][0] = r[2]; kh[2*p+1][1] = r[3];
            }
#pragma unroll
            for (int nt = 0; nt < 8; nt++)
                mma_f16(s4[nt], qf[kt], kh[nt]);
        }

        // ---- online softmax ----
        float mx0 = -CUDART_INF_F, mx1 = -CUDART_INF_F;
#pragma unroll
        for (int nt = 0; nt < 8; nt++) {
            mx0 = fmaxf(mx0, fmaxf(s4[nt][0], s4[nt][1]));
            mx1 = fmaxf(mx1, fmaxf(s4[nt][2], s4[nt][3]));
        }
        mx0 = fmaxf(mx0, __shfl_xor_sync(0xffffffffu, mx0, 1));
        mx0 = fmaxf(mx0, __shfl_xor_sync(0xffffffffu, mx0, 2));
        mx1 = fmaxf(mx1, __shfl_xor_sync(0xffffffffu, mx1, 1));
        mx1 = fmaxf(mx1, __shfl_xor_sync(0xffffffffu, mx1, 2));

        float mn0 = fmaxf(m0, mx0), mn1 = fmaxf(m1, mx1);
        float a0 = __expf(m0 - mn0), a1 = __expf(m1 - mn1);
        m0 = mn0; m1 = mn1;

        uint32_t pa[4][4];
        float sum0 = 0.0f, sum1 = 0.0f;
#pragma unroll
        for (int jj = 0; jj < 4; jj++) {
            float p00 = __expf(s4[2*jj][0]   - mn0), p01 = __expf(s4[2*jj][1]   - mn0);
            float p02 = __expf(s4[2*jj][2]   - mn1), p03 = __expf(s4[2*jj][3]   - mn1);
            float p10 = __expf(s4[2*jj+1][0] - mn0), p11 = __expf(s4[2*jj+1][1] - mn0);
            float p12 = __expf(s4[2*jj+1][2] - mn1), p13 = __expf(s4[2*jj+1][3] - mn1);
            pa[jj][0] = packh(p00, p01);
            pa[jj][1] = packh(p02, p03);
            pa[jj][2] = packh(p10, p11);
            pa[jj][3] = packh(p12, p13);
            // accumulate l from ROUNDED p so P rounding cancels with numerator
            float2 f;
            f = __half22float2(*(__half2*)&pa[jj][0]); sum0 += f.x + f.y;
            f = __half22float2(*(__half2*)&pa[jj][2]); sum0 += f.x + f.y;
            f = __half22float2(*(__half2*)&pa[jj][1]); sum1 += f.x + f.y;
            f = __half22float2(*(__half2*)&pa[jj][3]); sum1 += f.x + f.y;
        }
        sum0 += __shfl_xor_sync(0xffffffffu, sum0, 1);
        sum0 += __shfl_xor_sync(0xffffffffu, sum0, 2);
        sum1 += __shfl_xor_sync(0xffffffffu, sum1, 1);
        sum1 += __shfl_xor_sync(0xffffffffu, sum1, 2);
        l0 = l0 * a0 + sum0;
        l1 = l1 * a1 + sum1;
#pragma unroll
        for (int nt = 0; nt < 8; nt++) {
            O[nt][0] *= a0; O[nt][1] *= a0; O[nt][2] *= a1; O[nt][3] *= a1;
        }

        // ---- O += P V ----
#pragma unroll
        for (int kt = 0; kt < 4; kt++) {
#pragma unroll
            for (int p = 0; p < 4; p++) {
                uint32_t r[4];
                ldsm4t(r, sV + ((kt * 16 + vr) * AST + p * 16 + vc) * 2);
                mma_f16(O[2*p],   pa[kt], r);
                mma_f16(O[2*p+1], pa[kt], r + 2);
            }
        }
    }

    // ---- epilogue: normalize, write bf16 hi/lo ----
    const float inv0 = 1.0f / l0, inv1 = 1.0f / l1;
    const int r = lane >> 2, q = lane & 3;
    const int t0 = qt * 128 + wid * 16 + r;
#pragma unroll
    for (int nt = 0; nt < 8; nt++) {
        int d = nt * 8 + 2 * q;
        size_t i0 = ((size_t)(t0 * 2 + b)) * EMBED + h * 64 + d;
        size_t i1 = ((size_t)((t0 + 8) * 2 + b)) * EMBED + h * 64 + d;
        store_hilo(ohi, olo, i0, O[nt][0] * inv0, O[nt][1] * inv0);
        store_hilo(ohi, olo, i1, O[nt][2] * inv1, O[nt][3] * inv1);
    }
}

// ---------------------------------------------------------------------------
extern "C" void kernel_launch(void* const* d_in, const int* in_sizes, int n_in,
                              void* d_out, int out_size)
{
    const float* x     = (const float*)d_in[0];
    const float* w_in  = (const float*)d_in[1];
    const float* b_in  = (const float*)d_in[2];
    const float* w_out = (const float*)d_in[3];
    const float* b_out = (const float*)d_in[4];
    float* out = (float*)d_out;

    void *xhi, *xlo, *winhi, *winlo, *wohi, *wolo, *qkvh, *ahi, *alo;
    cudaGetSymbolAddress(&xhi, g_xhi);     cudaGetSymbolAddress(&xlo, g_xlo);
    cudaGetSymbolAddress(&winhi, g_winhi); cudaGetSymbolAddress(&winlo, g_winlo);
    cudaGetSymbolAddress(&wohi, g_wohi);   cudaGetSymbolAddress(&wolo, g_wolo);
    cudaGetSymbolAddress(&qkvh, g_qkvh);
    cudaGetSymbolAddress(&ahi, g_ahi);     cudaGetSymbolAddress(&alo, g_alo);

    const int gemm_smem = 2 * GSTAGE;                 // 81920
    const int attn_smem = QSTG + 4 * ATBF;            // 55296
    cudaFuncSetAttribute(gemm_mma<0>,
        cudaFuncAttributeMaxDynamicSharedMemorySize, gemm_smem);
    cudaFuncSetAttribute(gemm_mma<2>,
        cudaFuncAttributeMaxDynamicSharedMemorySize, gemm_smem);
    cudaFuncSetAttribute(attn_f16,
        cudaFuncAttributeMaxDynamicSharedMemorySize, attn_smem);

    int n4 = MROWS * EMBED / 4;
    split_bf16<<<(n4 + 255) / 256, 256>>>(x, (__nv_bfloat16*)xhi,
                                          (__nv_bfloat16*)xlo, n4);
    n4 = QKV_N * EMBED / 4;
    split_bf16<<<(n4 + 255) / 256, 256>>>(w_in, (__nv_bfloat16*)winhi,
                                          (__nv_bfloat16*)winlo, n4);
    n4 = EMBED * EMBED / 4;
    split_bf16<<<(n4 + 255) / 256, 256>>>(w_out, (__nv_bfloat16*)wohi,
                                          (__nv_bfloat16*)wolo, n4);

    // 1) QKV projection -> fp16 qkv
    gemm_mma<2><<<dim3(QKV_N / 128, MROWS / 128), 256, gemm_smem>>>(
        (const __nv_bfloat16*)xhi, (const __nv_bfloat16*)xlo,
        (const __nv_bfloat16*)winhi, (const __nv_bfloat16*)winlo,
        b_in, nullptr, (__half*)qkvh, QKV_N, EMBED);

    // 2) attention -> bf16 hi/lo
    attn_f16<<<dim3(TLEN / 128, BSZ * NHEAD), 256, attn_smem>>>(
        (const __half*)qkvh, (__nv_bfloat16*)ahi, (__nv_bfloat16*)alo);

    // 3) output projection -> fp32 out
    gemm_mma<0><<<dim3(EMBED / 128, MROWS / 128), 256, gemm_smem>>>(
        (const __nv_bfloat16*)ahi, (const __nv_bfloat16*)alo,
        (const __nv_bfloat16*)wohi, (const __nv_bfloat16*)wolo,
        b_out, out, nullptr, EMBED, EMBED);
}